// round 4
// baseline (speedup 1.0000x reference)
#include <cuda_runtime.h>
#include <cuda_bf16.h>
#include <stdint.h>
#include <math.h>

#define BATCH 256
#define NU    300
#define LIN   608
#define FLT   19
#define POOL  7
#define LP    84
#define HID   100
#define NCLS  50
#define EPSV  1e-5f

#define MTILES 19            // 304 unit rows
#define KSTEPS 5             // 5 x k16 = 80 >= 76
#define NCHUNK 24            // pools per B chunk

typedef unsigned long long u64;

// scratch (device globals)
__device__ float g_y[NU * LP * BATCH];   // [u][f][b]
__device__ float g_z[NU * BATCH];        // [u][b]

// ---------------------------------------------------------------------------
// smem byte offsets (dynamic smem)
// ---------------------------------------------------------------------------
#define ASZ    (MTILES * KSTEPS * 512)        // 48640 per split
#define BSZ    (NCHUNK * KSTEPS * 256)        // 30720 per split
#define SA_HI  0
#define SA_LO  (SA_HI + ASZ)                  // 48640
#define SB_HI  (SA_LO + ASZ)                  // 97280
#define SB_LO  (SB_HI + BSZ)                  // 128000
#define SXH    (SB_LO + BSZ)                  // 158720  (2432 bf16)
#define SXL    (SXH + 4864)                   // 163584
#define SBN_S  (SXL + 4864)                   // 168448  (300 f32)
#define SBN_C  (SBN_S + 1200)                 // 169648
#define SMTOT  (SBN_C + 1200)                 // 170848

__device__ __forceinline__ uint32_t smem_u32(const void* p) {
    uint32_t a;
    asm("{ .reg .u64 t; cvta.to.shared.u64 t, %1; cvt.u32.u64 %0, t; }"
        : "=r"(a) : "l"(p));
    return a;
}

#define LDSM4(r, a) \
    asm volatile("ldmatrix.sync.aligned.m8n8.x4.shared.b16 {%0,%1,%2,%3}, [%4];" \
        : "=r"((r)[0]), "=r"((r)[1]), "=r"((r)[2]), "=r"((r)[3]) : "r"(a))
#define LDSM2(r, a) \
    asm volatile("ldmatrix.sync.aligned.m8n8.x2.shared.b16 {%0,%1}, [%2];" \
        : "=r"((r)[0]), "=r"((r)[1]) : "r"(a))

__device__ __forceinline__ void mma16816(float* c, const uint32_t* a, const uint32_t* b) {
    asm volatile(
        "mma.sync.aligned.m16n8k16.row.col.f32.bf16.bf16.f32 "
        "{%0,%1,%2,%3}, {%4,%5,%6,%7}, {%8,%9}, {%0,%1,%2,%3};"
        : "+f"(c[0]), "+f"(c[1]), "+f"(c[2]), "+f"(c[3])
        : "r"(a[0]), "r"(a[1]), "r"(a[2]), "r"(a[3]), "r"(b[0]), "r"(b[1]));
}

// ---------------------------------------------------------------------------
// Kernel A: conv as warp-HMMA GEMM (split-bf16 3-pass) + fused BN/exp/maxpool
// grid 256 (batch), block 256 (8 warps). Pool-major B: one n8 tile == one pool.
// ---------------------------------------------------------------------------
__global__ __launch_bounds__(256, 1) void conv_mma_kernel(
    const float* __restrict__ x,  const float* __restrict__ w1,
    const float* __restrict__ b1, const float* __restrict__ g1,
    const float* __restrict__ be1,const float* __restrict__ m1,
    const float* __restrict__ v1)
{
    extern __shared__ __align__(128) char smem[];
    const uint32_t sb = smem_u32(smem);

    const int tid  = threadIdx.x;
    const int wid  = tid >> 5;
    const int lane = tid & 31;
    const int b    = blockIdx.x;

    __nv_bfloat16* xh = reinterpret_cast<__nv_bfloat16*>(smem + SXH);
    __nv_bfloat16* xl = reinterpret_cast<__nv_bfloat16*>(smem + SXL);
    float* s1s = reinterpret_cast<float*>(smem + SBN_S);
    float* c1s = reinterpret_cast<float*>(smem + SBN_C);

    // --- x load + hi/lo split ---
    {
        const float* xg = x + (size_t)b * (4 * LIN);
        for (int i = tid; i < 4 * LIN; i += 256) {
            const float v = xg[i];
            const __nv_bfloat16 h = __float2bfloat16(v);
            xh[i] = h;
            xl[i] = __float2bfloat16(v - __bfloat162float(h));
        }
    }
    // --- BN constants ---
    for (int i = tid; i < NU; i += 256) {
        const float s = g1[i] * rsqrtf(v1[i] + EPSV);
        s1s[i] = s;
        c1s[i] = (b1[i] - m1[i]) * s + be1[i];
    }
    // --- A build: W (304x80, zero-padded) in ldmatrix-mat layout, hi/lo ---
    {
        __nv_bfloat16* aH = reinterpret_cast<__nv_bfloat16*>(smem + SA_HI);
        __nv_bfloat16* aL = reinterpret_cast<__nv_bfloat16*>(smem + SA_LO);
        for (int i = tid; i < 304 * 80; i += 256) {
            const int ul = i / 80;
            const int k  = i % 80;
            float v = 0.f;
            if (ul < NU && k < 76) v = w1[ul * 76 + k];
            const __nv_bfloat16 h = __float2bfloat16(v);
            const __nv_bfloat16 l = __float2bfloat16(v - __bfloat162float(h));
            const int mt  = ul >> 4, s = k >> 4;
            const int mat = ((ul & 15) >> 3) | (((k & 15) >> 3) << 1);
            const int off = ((((mt * KSTEPS + s) << 2) + mat) << 6)
                            + ((ul & 7) << 3) + (k & 7);   // in bf16 units
            aH[off] = h;
            aL[off] = l;
        }
    }
    __syncthreads();

    // --- loop over 4 pool-chunks ---
    for (int nt = 0; nt < 4; nt++) {
        const int npools = (nt < 3) ? NCHUNK : (LP - 3 * NCHUNK);   // 24,24,24,12

        // build B chunk: pool-major im2col, hi/lo
        {
            __nv_bfloat16* bH = reinterpret_cast<__nv_bfloat16*>(smem + SB_HI);
            __nv_bfloat16* bL = reinterpret_cast<__nv_bfloat16*>(smem + SB_LO);
            const int tot = npools * 8 * 80;
            for (int i = tid; i < tot; i += 256) {
                const int p  = i / 640;
                const int r  = i % 640;
                const int j  = r / 80;        // slot 0..7
                const int k  = r % 80;
                const int jj = (j == 7) ? 0 : j;   // slot 7 duplicates slot 0
                __nv_bfloat16 vh = __float2bfloat16(0.f);
                __nv_bfloat16 vl = vh;
                if (k < 76) {
                    const int c  = k / FLT, kk = k % FLT;
                    const int xi = c * LIN + 7 * (nt * NCHUNK + p) + jj + kk;
                    vh = xh[xi];
                    vl = xl[xi];
                }
                const int off = (((p * KSTEPS + (k >> 4)) << 1) + ((k & 15) >> 3)) * 128
                                + (j << 4) + ((k & 7) << 1);   // bytes
                *reinterpret_cast<__nv_bfloat16*>(smem + SB_HI + off) = vh;
                *reinterpret_cast<__nv_bfloat16*>(smem + SB_LO + off) = vl;
            }
            (void)bH; (void)bL;
        }
        __syncthreads();

        // compute: all warps loop mtiles; warp w handles pools w, w+8, ...
        const uint32_t aBaseH = sb + SA_HI + lane * 16;
        const uint32_t aBaseL = sb + SA_LO + lane * 16;
        const int L2 = lane & 15;
        const uint32_t bOff = ((L2 >> 3) << 7) + ((L2 & 7) << 4);

        for (int mt = 0; mt < MTILES; mt++) {
            uint32_t ah[KSTEPS][4], al[KSTEPS][4];
#pragma unroll
            for (int s = 0; s < KSTEPS; s++) {
                LDSM4(ah[s], aBaseH + (mt * KSTEPS + s) * 512);
                LDSM4(al[s], aBaseL + (mt * KSTEPS + s) * 512);
            }
            for (int pt = wid; pt < npools; pt += 8) {
                float acc[4] = {0.f, 0.f, 0.f, 0.f};
#pragma unroll
                for (int s = 0; s < KSTEPS; s++) {
                    uint32_t bh[2], bl[2];
                    const uint32_t tb = (pt * KSTEPS + s) * 256 + bOff;
                    LDSM2(bh, sb + SB_HI + tb);
                    LDSM2(bl, sb + SB_LO + tb);
                    mma16816(acc, ah[s], bh);
                    mma16816(acc, ah[s], bl);
                    mma16816(acc, al[s], bh);
                }
                // pool max within n8 tile (cols = 7 positions + 1 dup)
                float mA = fmaxf(acc[0], acc[1]);     // row g
                float mB = fmaxf(acc[2], acc[3]);     // row g+8
                mA = fmaxf(mA, __shfl_xor_sync(0xFFFFFFFFu, mA, 1));
                mA = fmaxf(mA, __shfl_xor_sync(0xFFFFFFFFu, mA, 2));
                mB = fmaxf(mB, __shfl_xor_sync(0xFFFFFFFFu, mB, 1));
                mB = fmaxf(mB, __shfl_xor_sync(0xFFFFFFFFu, mB, 2));
                if ((lane & 3) == 0) {
                    const int g  = lane >> 2;
                    const int u0 = mt * 16 + g;
                    const int u1 = u0 + 8;
                    const int f  = nt * NCHUNK + pt;
                    if (u0 < NU)
                        g_y[((size_t)u0 * LP + f) * BATCH + b] =
                            __expf(fmaf(mA, s1s[u0], c1s[u0]));
                    if (u1 < NU)
                        g_y[((size_t)u1 * LP + f) * BATCH + b] =
                            __expf(fmaf(mB, s1s[u1], c1s[u1]));
                }
            }
        }
        __syncthreads();
    }
}

// ---------------------------------------------------------------------------
// packed f32x2 helpers (MLP kernel)
// ---------------------------------------------------------------------------
__device__ __forceinline__ u64 pack2(float a, float b) {
    u64 r;
    asm("mov.b64 %0, {%1, %2};" : "=l"(r) : "f"(a), "f"(b));
    return r;
}
__device__ __forceinline__ void fma2(u64 &d, u64 a, u64 b) {
    asm("fma.rn.f32x2 %0, %1, %2, %0;" : "+l"(d) : "l"(a), "l"(b));
}
__device__ __forceinline__ void unpack2(float &lo, float &hi, u64 v) {
    unsigned a, b;
    asm("mov.b64 {%0, %1}, %2;" : "=r"(a), "=r"(b) : "l"(v));
    lo = __uint_as_float(a); hi = __uint_as_float(b);
}

// ---------------------------------------------------------------------------
// Kernel B: per-unit MLP 84->100 (BN+ReLU) -> 100->1 (BN+ReLU)  ->  z[u][b]
// ---------------------------------------------------------------------------
__global__ __launch_bounds__(BATCH) void unit_mlp_kernel(
    const float* __restrict__ w2, const float* __restrict__ b2,
    const float* __restrict__ g2, const float* __restrict__ be2,
    const float* __restrict__ m2, const float* __restrict__ v2,
    const float* __restrict__ w3, const float* __restrict__ b3,
    const float* __restrict__ g3, const float* __restrict__ be3,
    const float* __restrict__ m3, const float* __restrict__ v3)
{
    __shared__ __align__(16) float w2s[HID * LP];
    __shared__ float s2s[HID], c2s[HID], w3s[HID];

    const int u   = blockIdx.x;
    const int tid = threadIdx.x;

    for (int i = tid; i < HID * LP; i += BATCH)
        w2s[i] = w2[u * HID * LP + i];
    if (tid < HID) {
        const int idx = u * HID + tid;
        float s = g2[idx] * rsqrtf(v2[idx] + EPSV);
        s2s[tid] = s;
        c2s[tid] = (b2[idx] - m2[idx]) * s + be2[idx];
        w3s[tid] = w3[idx];
    }
    __syncthreads();

    u64 yv2[LP / 2];
#pragma unroll
    for (int fp = 0; fp < LP / 2; fp++) {
        const float a  = g_y[u * (LP * BATCH) + (2 * fp) * BATCH + tid];
        const float bb = g_y[u * (LP * BATCH) + (2 * fp + 1) * BATCH + tid];
        yv2[fp] = pack2(a, bb);
    }

    float zacc = 0.0f;
#pragma unroll 1
    for (int o = 0; o < HID; o++) {
        const float4* wrow = reinterpret_cast<const float4*>(&w2s[o * LP]);
        u64 a0 = 0ULL, a1 = 0ULL;
#pragma unroll
        for (int j = 0; j < LP / 4; j++) {
            float4 v = wrow[j];
            u64 w01 = pack2(v.x, v.y);
            u64 w23 = pack2(v.z, v.w);
            fma2(a0, yv2[2 * j], w01);
            fma2(a1, yv2[2 * j + 1], w23);
        }
        float l0, h0, l1, h1;
        unpack2(l0, h0, a0);
        unpack2(l1, h1, a1);
        const float dsum = (l0 + h0) + (l1 + h1);
        const float hv = fmaxf(fmaf(dsum, s2s[o], c2s[o]), 0.0f);
        zacc = fmaf(hv, w3s[o], zacc);
    }

    const float s3 = g3[u] * rsqrtf(v3[u] + EPSV);
    const float z  = fmaf(zacc + b3[u] - m3[u], s3, be3[u]);
    g_z[u * BATCH + tid] = fmaxf(z, 0.0f);
}

// ---------------------------------------------------------------------------
// Kernel C: out[b][c] = sum_u z[u][b] * wf[c][u] + bf[c]
// ---------------------------------------------------------------------------
__global__ __launch_bounds__(BATCH) void final_linear_kernel(
    const float* __restrict__ wf, const float* __restrict__ bf,
    float* __restrict__ out)
{
    __shared__ float wfs[NU];
    const int c   = blockIdx.x;
    const int tid = threadIdx.x;

    for (int i = tid; i < NU; i += BATCH)
        wfs[i] = wf[c * NU + i];
    __syncthreads();

    float acc = bf[c];
#pragma unroll 4
    for (int u = 0; u < NU; u++)
        acc = fmaf(g_z[u * BATCH + tid], wfs[u], acc);

    out[tid * NCLS + c] = acc;
}

// ---------------------------------------------------------------------------
extern "C" void kernel_launch(void* const* d_in, const int* in_sizes, int n_in,
                              void* d_out, int out_size)
{
    const float* x   = (const float*)d_in[0];
    const float* w1  = (const float*)d_in[1];
    const float* b1  = (const float*)d_in[2];
    const float* g1  = (const float*)d_in[3];
    const float* be1 = (const float*)d_in[4];
    const float* m1  = (const float*)d_in[5];
    const float* v1  = (const float*)d_in[6];
    const float* w2  = (const float*)d_in[7];
    const float* b2  = (const float*)d_in[8];
    const float* g2  = (const float*)d_in[9];
    const float* be2 = (const float*)d_in[10];
    const float* m2  = (const float*)d_in[11];
    const float* v2  = (const float*)d_in[12];
    const float* w3  = (const float*)d_in[13];
    const float* b3  = (const float*)d_in[14];
    const float* g3  = (const float*)d_in[15];
    const float* be3 = (const float*)d_in[16];
    const float* m3  = (const float*)d_in[17];
    const float* v3  = (const float*)d_in[18];
    const float* wf  = (const float*)d_in[19];
    const float* bf  = (const float*)d_in[20];
    float* out = (float*)d_out;

    cudaFuncSetAttribute(conv_mma_kernel,
                         cudaFuncAttributeMaxDynamicSharedMemorySize, SMTOT);

    conv_mma_kernel<<<BATCH, 256, SMTOT>>>(x, w1, b1, g1, be1, m1, v1);
    unit_mlp_kernel<<<NU, BATCH>>>(w2, b2, g2, be2, m2, v2,
                                   w3, b3, g3, be3, m3, v3);
    final_linear_kernel<<<NCLS, BATCH>>>(wf, bf, out);
}

// round 5
// speedup vs baseline: 1.3740x; 1.3740x over previous
#include <cuda_runtime.h>
#include <cuda_bf16.h>
#include <stdint.h>
#include <math.h>

#define BATCH 256
#define NU    300
#define LIN   608
#define FLT   19
#define POOL  7
#define LP    84
#define HID   100
#define NCLS  50
#define EPSV  1e-5f

#define MTILES 19            // 304 unit rows
#define KSTEPS 5             // 5 x k16 = 80 >= 76
#define NCHUNK 24            // pools per B chunk
#define CTHREADS 384         // 12 warps
#define BPC   2              // batches per CTA (grid 128)

typedef unsigned long long u64;

// scratch (device globals)
__device__ float g_y[NU * LP * BATCH];   // [u][f][b]
__device__ float g_z[NU * BATCH];        // [u][b]

// ---------------------------------------------------------------------------
// smem byte offsets (dynamic smem)
// ---------------------------------------------------------------------------
#define ASZ    (MTILES * KSTEPS * 512)        // 48640 per split
#define BSZ    (NCHUNK * KSTEPS * 256)        // 30720 per split
#define SA_HI  0
#define SA_LO  (SA_HI + ASZ)                  // 48640
#define SB_HI  (SA_LO + ASZ)                  // 97280
#define SB_LO  (SB_HI + BSZ)                  // 128000
#define SXH    (SB_LO + BSZ)                  // 158720  (2432 bf16)
#define SXL    (SXH + 4864)                   // 163584
#define SBN_S  (SXL + 4864)                   // 168448  (300 f32)
#define SBN_C  (SBN_S + 1200)                 // 169648
#define SMTOT  (SBN_C + 1200)                 // 170848

__device__ __forceinline__ uint32_t smem_u32(const void* p) {
    uint32_t a;
    asm("{ .reg .u64 t; cvta.to.shared.u64 t, %1; cvt.u32.u64 %0, t; }"
        : "=r"(a) : "l"(p));
    return a;
}

#define LDSM4(r, a) \
    asm volatile("ldmatrix.sync.aligned.m8n8.x4.shared.b16 {%0,%1,%2,%3}, [%4];" \
        : "=r"((r)[0]), "=r"((r)[1]), "=r"((r)[2]), "=r"((r)[3]) : "r"(a))
#define LDSM2(r, a) \
    asm volatile("ldmatrix.sync.aligned.m8n8.x2.shared.b16 {%0,%1}, [%2];" \
        : "=r"((r)[0]), "=r"((r)[1]) : "r"(a))

__device__ __forceinline__ void mma16816(float* c, const uint32_t* a, const uint32_t* b) {
    asm volatile(
        "mma.sync.aligned.m16n8k16.row.col.f32.bf16.bf16.f32 "
        "{%0,%1,%2,%3}, {%4,%5,%6,%7}, {%8,%9}, {%0,%1,%2,%3};"
        : "+f"(c[0]), "+f"(c[1]), "+f"(c[2]), "+f"(c[3])
        : "r"(a[0]), "r"(a[1]), "r"(a[2]), "r"(a[3]), "r"(b[0]), "r"(b[1]));
}

// ---------------------------------------------------------------------------
// Kernel A: conv as warp-HMMA GEMM (split-bf16 3-pass) + fused BN/exp/maxpool
// grid 128 (2 batches each), block 384 (12 warps).
// Pool-major B: one n8 tile == one pool (7 positions + 1 dup).
// A (weights) built once per CTA; B fragments register-resident per chunk.
// ---------------------------------------------------------------------------
__global__ __launch_bounds__(CTHREADS, 1) void conv_mma_kernel(
    const float* __restrict__ x,  const float* __restrict__ w1,
    const float* __restrict__ b1, const float* __restrict__ g1,
    const float* __restrict__ be1,const float* __restrict__ m1,
    const float* __restrict__ v1)
{
    extern __shared__ __align__(128) char smem[];
    const uint32_t sb = smem_u32(smem);

    const int tid  = threadIdx.x;
    const int wid  = tid >> 5;
    const int lane = tid & 31;

    __nv_bfloat16* xh = reinterpret_cast<__nv_bfloat16*>(smem + SXH);
    __nv_bfloat16* xl = reinterpret_cast<__nv_bfloat16*>(smem + SXL);
    float* s1s = reinterpret_cast<float*>(smem + SBN_S);
    float* c1s = reinterpret_cast<float*>(smem + SBN_C);

    // --- BN constants (once) ---
    for (int i = tid; i < NU; i += CTHREADS) {
        const float s = g1[i] * rsqrtf(v1[i] + EPSV);
        s1s[i] = s;
        c1s[i] = (b1[i] - m1[i]) * s + be1[i];
    }
    // --- A build (once): W (304x80, zero-padded), ldmatrix-mat layout, hi/lo ---
    {
        __nv_bfloat16* aH = reinterpret_cast<__nv_bfloat16*>(smem + SA_HI);
        __nv_bfloat16* aL = reinterpret_cast<__nv_bfloat16*>(smem + SA_LO);
        for (int i = tid; i < 304 * 80; i += CTHREADS) {
            const int ul = i / 80;
            const int k  = i % 80;
            float v = 0.f;
            if (ul < NU && k < 76) v = w1[ul * 76 + k];
            const __nv_bfloat16 h = __float2bfloat16(v);
            const __nv_bfloat16 l = __float2bfloat16(v - __bfloat162float(h));
            const int mt  = ul >> 4, s = k >> 4;
            const int mat = ((ul & 15) >> 3) | (((k & 15) >> 3) << 1);
            const int off = ((((mt * KSTEPS + s) << 2) + mat) << 6)
                            + ((ul & 7) << 3) + (k & 7);   // bf16 units
            aH[off] = h;
            aL[off] = l;
        }
    }

    const uint32_t aBaseH = sb + SA_HI + lane * 16;
    const uint32_t aBaseL = sb + SA_LO + lane * 16;
    const int L2 = lane & 15;
    const uint32_t bOff = ((L2 >> 3) << 7) + ((L2 & 7) << 4);

    for (int bi = 0; bi < BPC; bi++) {
        const int b = blockIdx.x * BPC + bi;

        // --- x load + hi/lo split ---
        {
            const float* xg = x + (size_t)b * (4 * LIN);
            for (int i = tid; i < 4 * LIN; i += CTHREADS) {
                const float v = xg[i];
                const __nv_bfloat16 h = __float2bfloat16(v);
                xh[i] = h;
                xl[i] = __float2bfloat16(v - __bfloat162float(h));
            }
        }
        __syncthreads();

        // --- loop over 4 pool-chunks ---
        for (int nt = 0; nt < 4; nt++) {
            const int npools = (nt < 3) ? NCHUNK : (LP - 3 * NCHUNK);   // 24,24,24,12

            // build B chunk: pool-major im2col, hi/lo splits
            {
                const int tot = npools * 8 * 80;
                for (int i = tid; i < tot; i += CTHREADS) {
                    const int p  = i / 640;
                    const int r  = i % 640;
                    const int j  = r / 80;           // slot 0..7
                    const int k  = r % 80;
                    const int jj = (j == 7) ? 0 : j; // slot 7 duplicates slot 0
                    __nv_bfloat16 vh = __float2bfloat16(0.f);
                    __nv_bfloat16 vl = vh;
                    if (k < 76) {
                        const int c  = k / FLT, kk = k % FLT;
                        const int xi = c * LIN + 7 * (nt * NCHUNK + p) + jj + kk;
                        vh = xh[xi];
                        vl = xl[xi];
                    }
                    const int off = (((p * KSTEPS + (k >> 4)) << 1) + ((k & 15) >> 3)) * 128
                                    + (j << 4) + ((k & 7) << 1);   // bytes
                    *reinterpret_cast<__nv_bfloat16*>(smem + SB_HI + off) = vh;
                    *reinterpret_cast<__nv_bfloat16*>(smem + SB_LO + off) = vl;
                }
            }
            __syncthreads();

            // --- B fragments -> registers (once per chunk) ---
            uint32_t bh[2][KSTEPS][2], bl[2][KSTEPS][2];
#pragma unroll
            for (int r = 0; r < 2; r++) {
                const int pt = wid + 12 * r;
                if (pt < npools) {
#pragma unroll
                    for (int s = 0; s < KSTEPS; s++) {
                        const uint32_t tb = (pt * KSTEPS + s) * 256 + bOff;
                        LDSM2(bh[r][s], sb + SB_HI + tb);
                        LDSM2(bl[r][s], sb + SB_LO + tb);
                    }
                }
            }

            // --- stream A over m-tiles; 2 independent acc chains per warp ---
            for (int mt = 0; mt < MTILES; mt++) {
                uint32_t ah[KSTEPS][4], al[KSTEPS][4];
#pragma unroll
                for (int s = 0; s < KSTEPS; s++) {
                    LDSM4(ah[s], aBaseH + (mt * KSTEPS + s) * 512);
                    LDSM4(al[s], aBaseL + (mt * KSTEPS + s) * 512);
                }
                float acc[2][4];
#pragma unroll
                for (int r = 0; r < 2; r++)
#pragma unroll
                    for (int q = 0; q < 4; q++) acc[r][q] = 0.f;

#pragma unroll
                for (int s = 0; s < KSTEPS; s++) {
#pragma unroll
                    for (int r = 0; r < 2; r++) {
                        if (wid + 12 * r < npools) {
                            mma16816(acc[r], ah[s], bh[r][s]);
                            mma16816(acc[r], ah[s], bl[r][s]);
                            mma16816(acc[r], al[s], bh[r][s]);
                        }
                    }
                }

#pragma unroll
                for (int r = 0; r < 2; r++) {
                    const int pt = wid + 12 * r;
                    if (pt < npools) {
                        float mA = fmaxf(acc[r][0], acc[r][1]);   // row g
                        float mB = fmaxf(acc[r][2], acc[r][3]);   // row g+8
                        mA = fmaxf(mA, __shfl_xor_sync(0xFFFFFFFFu, mA, 1));
                        mA = fmaxf(mA, __shfl_xor_sync(0xFFFFFFFFu, mA, 2));
                        mB = fmaxf(mB, __shfl_xor_sync(0xFFFFFFFFu, mB, 1));
                        mB = fmaxf(mB, __shfl_xor_sync(0xFFFFFFFFu, mB, 2));
                        if ((lane & 3) == 0) {
                            const int g  = lane >> 2;
                            const int u0 = mt * 16 + g;
                            const int u1 = u0 + 8;
                            const int f  = nt * NCHUNK + pt;
                            if (u0 < NU)
                                g_y[((size_t)u0 * LP + f) * BATCH + b] =
                                    __expf(fmaf(mA, s1s[u0], c1s[u0]));
                            if (u1 < NU)
                                g_y[((size_t)u1 * LP + f) * BATCH + b] =
                                    __expf(fmaf(mB, s1s[u1], c1s[u1]));
                        }
                    }
                }
            }
            __syncthreads();
        }
    }
}

// ---------------------------------------------------------------------------
// packed f32x2 helpers (MLP kernel)
// ---------------------------------------------------------------------------
__device__ __forceinline__ u64 pack2(float a, float b) {
    u64 r;
    asm("mov.b64 %0, {%1, %2};" : "=l"(r) : "f"(a), "f"(b));
    return r;
}
__device__ __forceinline__ void fma2(u64 &d, u64 a, u64 b) {
    asm("fma.rn.f32x2 %0, %1, %2, %0;" : "+l"(d) : "l"(a), "l"(b));
}
__device__ __forceinline__ void unpack2(float &lo, float &hi, u64 v) {
    unsigned a, b;
    asm("mov.b64 {%0, %1}, %2;" : "=r"(a), "=r"(b) : "l"(v));
    lo = __uint_as_float(a); hi = __uint_as_float(b);
}

// ---------------------------------------------------------------------------
// Kernel B: per-unit MLP 84->100 (BN+ReLU) -> 100->1 (BN+ReLU)  ->  z[u][b]
// ---------------------------------------------------------------------------
__global__ __launch_bounds__(BATCH) void unit_mlp_kernel(
    const float* __restrict__ w2, const float* __restrict__ b2,
    const float* __restrict__ g2, const float* __restrict__ be2,
    const float* __restrict__ m2, const float* __restrict__ v2,
    const float* __restrict__ w3, const float* __restrict__ b3,
    const float* __restrict__ g3, const float* __restrict__ be3,
    const float* __restrict__ m3, const float* __restrict__ v3)
{
    __shared__ __align__(16) float w2s[HID * LP];
    __shared__ float s2s[HID], c2s[HID], w3s[HID];

    const int u   = blockIdx.x;
    const int tid = threadIdx.x;

    for (int i = tid; i < HID * LP; i += BATCH)
        w2s[i] = w2[u * HID * LP + i];
    if (tid < HID) {
        const int idx = u * HID + tid;
        float s = g2[idx] * rsqrtf(v2[idx] + EPSV);
        s2s[tid] = s;
        c2s[tid] = (b2[idx] - m2[idx]) * s + be2[idx];
        w3s[tid] = w3[idx];
    }
    __syncthreads();

    u64 yv2[LP / 2];
#pragma unroll
    for (int fp = 0; fp < LP / 2; fp++) {
        const float a  = g_y[u * (LP * BATCH) + (2 * fp) * BATCH + tid];
        const float bb = g_y[u * (LP * BATCH) + (2 * fp + 1) * BATCH + tid];
        yv2[fp] = pack2(a, bb);
    }

    float zacc = 0.0f;
#pragma unroll 1
    for (int o = 0; o < HID; o++) {
        const float4* wrow = reinterpret_cast<const float4*>(&w2s[o * LP]);
        u64 a0 = 0ULL, a1 = 0ULL;
#pragma unroll
        for (int j = 0; j < LP / 4; j++) {
            float4 v = wrow[j];
            u64 w01 = pack2(v.x, v.y);
            u64 w23 = pack2(v.z, v.w);
            fma2(a0, yv2[2 * j], w01);
            fma2(a1, yv2[2 * j + 1], w23);
        }
        float l0, h0, l1, h1;
        unpack2(l0, h0, a0);
        unpack2(l1, h1, a1);
        const float dsum = (l0 + h0) + (l1 + h1);
        const float hv = fmaxf(fmaf(dsum, s2s[o], c2s[o]), 0.0f);
        zacc = fmaf(hv, w3s[o], zacc);
    }

    const float s3 = g3[u] * rsqrtf(v3[u] + EPSV);
    const float z  = fmaf(zacc + b3[u] - m3[u], s3, be3[u]);
    g_z[u * BATCH + tid] = fmaxf(z, 0.0f);
}

// ---------------------------------------------------------------------------
// Kernel C: out[b][c] = sum_u z[u][b] * wf[c][u] + bf[c]
// ---------------------------------------------------------------------------
__global__ __launch_bounds__(BATCH) void final_linear_kernel(
    const float* __restrict__ wf, const float* __restrict__ bf,
    float* __restrict__ out)
{
    __shared__ float wfs[NU];
    const int c   = blockIdx.x;
    const int tid = threadIdx.x;

    for (int i = tid; i < NU; i += BATCH)
        wfs[i] = wf[c * NU + i];
    __syncthreads();

    float acc = bf[c];
#pragma unroll 4
    for (int u = 0; u < NU; u++)
        acc = fmaf(g_z[u * BATCH + tid], wfs[u], acc);

    out[tid * NCLS + c] = acc;
}

// ---------------------------------------------------------------------------
extern "C" void kernel_launch(void* const* d_in, const int* in_sizes, int n_in,
                              void* d_out, int out_size)
{
    const float* x   = (const float*)d_in[0];
    const float* w1  = (const float*)d_in[1];
    const float* b1  = (const float*)d_in[2];
    const float* g1  = (const float*)d_in[3];
    const float* be1 = (const float*)d_in[4];
    const float* m1  = (const float*)d_in[5];
    const float* v1  = (const float*)d_in[6];
    const float* w2  = (const float*)d_in[7];
    const float* b2  = (const float*)d_in[8];
    const float* g2  = (const float*)d_in[9];
    const float* be2 = (const float*)d_in[10];
    const float* m2  = (const float*)d_in[11];
    const float* v2  = (const float*)d_in[12];
    const float* w3  = (const float*)d_in[13];
    const float* b3  = (const float*)d_in[14];
    const float* g3  = (const float*)d_in[15];
    const float* be3 = (const float*)d_in[16];
    const float* m3  = (const float*)d_in[17];
    const float* v3  = (const float*)d_in[18];
    const float* wf  = (const float*)d_in[19];
    const float* bf  = (const float*)d_in[20];
    float* out = (float*)d_out;

    cudaFuncSetAttribute(conv_mma_kernel,
                         cudaFuncAttributeMaxDynamicSharedMemorySize, SMTOT);

    conv_mma_kernel<<<BATCH / BPC, CTHREADS, SMTOT>>>(x, w1, b1, g1, be1, m1, v1);
    unit_mlp_kernel<<<NU, BATCH>>>(w2, b2, g2, be2, m2, v2,
                                   w3, b3, g3, be3, m3, v3);
    final_linear_kernel<<<NCLS, BATCH>>>(wf, bf, out);
}

// round 6
// speedup vs baseline: 1.3849x; 1.0079x over previous
#include <cuda_runtime.h>
#include <cuda_bf16.h>
#include <stdint.h>
#include <math.h>

#define BATCH 256
#define NU    300
#define LIN   608
#define FLT   19
#define POOL  7
#define LP    84
#define HID   100
#define NCLS  50
#define EPSV  1e-5f

#define MTILES 19            // 304 unit rows
#define KSTEPS 5             // 5 x k16 = 80 >= 76
#define NCHUNK 24            // pools per B chunk
#define CTHREADS 384         // 12 warps
#define BPC   2              // batches per CTA (grid 128)

typedef unsigned long long u64;

// scratch (device globals)
__device__ float g_y[NU * LP * BATCH];   // [u][f][b]
__device__ float g_z[NU * BATCH];        // [u][b]

// ---------------------------------------------------------------------------
// smem byte offsets (dynamic smem)
// ---------------------------------------------------------------------------
#define ASZ    (MTILES * KSTEPS * 512)        // 48640 per split
#define BSZ    (NCHUNK * KSTEPS * 256)        // 30720 per split
#define SA_HI  0
#define SA_LO  (SA_HI + ASZ)
#define SB_HI  (SA_LO + ASZ)
#define SB_LO  (SB_HI + BSZ)
#define SXH    (SB_LO + BSZ)
#define SXL    (SXH + 4864)
#define SBN_S  (SXL + 4864)
#define SBN_C  (SBN_S + 1200)
#define SMTOT  (SBN_C + 1200)

__device__ __forceinline__ uint32_t smem_u32(const void* p) {
    uint32_t a;
    asm("{ .reg .u64 t; cvta.to.shared.u64 t, %1; cvt.u32.u64 %0, t; }"
        : "=r"(a) : "l"(p));
    return a;
}

#define LDSM4(r, a) \
    asm volatile("ldmatrix.sync.aligned.m8n8.x4.shared.b16 {%0,%1,%2,%3}, [%4];" \
        : "=r"((r)[0]), "=r"((r)[1]), "=r"((r)[2]), "=r"((r)[3]) : "r"(a))
#define LDSM2(r, a) \
    asm volatile("ldmatrix.sync.aligned.m8n8.x2.shared.b16 {%0,%1}, [%2];" \
        : "=r"((r)[0]), "=r"((r)[1]) : "r"(a))

__device__ __forceinline__ void mma16816(float* c, const uint32_t* a, const uint32_t* b) {
    asm volatile(
        "mma.sync.aligned.m16n8k16.row.col.f32.bf16.bf16.f32 "
        "{%0,%1,%2,%3}, {%4,%5,%6,%7}, {%8,%9}, {%0,%1,%2,%3};"
        : "+f"(c[0]), "+f"(c[1]), "+f"(c[2]), "+f"(c[3])
        : "r"(a[0]), "r"(a[1]), "r"(a[2]), "r"(a[3]), "r"(b[0]), "r"(b[1]));
}

// process one m-tile: interleaved 4-chain MMA stream, A prefetch hoisted
// before the acc-dependent epilogue.
#define PROC(MT, AHC, ALC, AHN, ALN) do {                                      \
    float acc[2][2][4];                                                        \
    _Pragma("unroll") for (int r = 0; r < 2; r++)                              \
    _Pragma("unroll") for (int s2 = 0; s2 < 2; s2++)                           \
    _Pragma("unroll") for (int q = 0; q < 4; q++) acc[r][s2][q] = 0.f;         \
    _Pragma("unroll") for (int t = 0; t < 15; t++) {                           \
        const int s = t / 3, pz = t % 3, sbk = t & 1;                          \
        mma16816(acc[0][sbk], pz == 2 ? (ALC)[s] : (AHC)[s],                   \
                 pz == 1 ? bl[0][s] : bh[0][s]);                               \
        if (use2)                                                              \
            mma16816(acc[1][sbk], pz == 2 ? (ALC)[s] : (AHC)[s],               \
                     pz == 1 ? bl[1][s] : bh[1][s]);                           \
    }                                                                          \
    if ((MT) + 1 < MTILES) {                                                   \
        _Pragma("unroll") for (int s = 0; s < KSTEPS; s++) {                   \
            LDSM4((AHN)[s], aBaseH + (((MT) + 1) * KSTEPS + s) * 512);         \
            LDSM4((ALN)[s], aBaseL + (((MT) + 1) * KSTEPS + s) * 512);         \
        }                                                                      \
    }                                                                          \
    _Pragma("unroll") for (int r = 0; r < 2; r++) {                            \
        if (r == 0 || use2) {                                                  \
            const float f0 = acc[r][0][0] + acc[r][1][0];                      \
            const float f1 = acc[r][0][1] + acc[r][1][1];                      \
            const float f2 = acc[r][0][2] + acc[r][1][2];                      \
            const float f3 = acc[r][0][3] + acc[r][1][3];                      \
            float mA = fmaxf(f0, f1), mB = fmaxf(f2, f3);                      \
            mA = fmaxf(mA, __shfl_xor_sync(0xFFFFFFFFu, mA, 1));               \
            mA = fmaxf(mA, __shfl_xor_sync(0xFFFFFFFFu, mA, 2));               \
            mB = fmaxf(mB, __shfl_xor_sync(0xFFFFFFFFu, mB, 1));               \
            mB = fmaxf(mB, __shfl_xor_sync(0xFFFFFFFFu, mB, 2));               \
            if ((lane & 3) == 0) {                                             \
                const int g  = lane >> 2;                                      \
                const int u0 = (MT) * 16 + g;                                  \
                const int u1 = u0 + 8;                                         \
                const int f  = nt * NCHUNK + wid + 12 * r;                     \
                if (u0 < NU)                                                   \
                    g_y[((size_t)u0 * LP + f) * BATCH + b] =                   \
                        __expf(fmaf(mA, s1s[u0], c1s[u0]));                    \
                if (u1 < NU)                                                   \
                    g_y[((size_t)u1 * LP + f) * BATCH + b] =                   \
                        __expf(fmaf(mB, s1s[u1], c1s[u1]));                    \
            }                                                                  \
        }                                                                      \
    }                                                                          \
} while (0)

// ---------------------------------------------------------------------------
// Kernel A: conv as warp-HMMA GEMM (split-bf16 3-pass) + fused BN/exp/maxpool
// ---------------------------------------------------------------------------
__global__ __launch_bounds__(CTHREADS, 1) void conv_mma_kernel(
    const float* __restrict__ x,  const float* __restrict__ w1,
    const float* __restrict__ b1, const float* __restrict__ g1,
    const float* __restrict__ be1,const float* __restrict__ m1,
    const float* __restrict__ v1)
{
    extern __shared__ __align__(128) char smem[];
    const uint32_t sb = smem_u32(smem);

    const int tid  = threadIdx.x;
    const int wid  = tid >> 5;
    const int lane = tid & 31;

    __nv_bfloat16* xh = reinterpret_cast<__nv_bfloat16*>(smem + SXH);
    __nv_bfloat16* xl = reinterpret_cast<__nv_bfloat16*>(smem + SXL);
    float* s1s = reinterpret_cast<float*>(smem + SBN_S);
    float* c1s = reinterpret_cast<float*>(smem + SBN_C);

    // --- BN constants (once) ---
    for (int i = tid; i < NU; i += CTHREADS) {
        const float s = g1[i] * rsqrtf(v1[i] + EPSV);
        s1s[i] = s;
        c1s[i] = (b1[i] - m1[i]) * s + be1[i];
    }
    // --- A build (once): W (304x80, zero-padded), ldmatrix-mat layout, hi/lo ---
    {
        __nv_bfloat16* aH = reinterpret_cast<__nv_bfloat16*>(smem + SA_HI);
        __nv_bfloat16* aL = reinterpret_cast<__nv_bfloat16*>(smem + SA_LO);
        for (int i = tid; i < 304 * 80; i += CTHREADS) {
            const int ul = i / 80;
            const int k  = i % 80;
            float v = 0.f;
            if (ul < NU && k < 76) v = w1[ul * 76 + k];
            const __nv_bfloat16 h = __float2bfloat16(v);
            const __nv_bfloat16 l = __float2bfloat16(v - __bfloat162float(h));
            const int mt  = ul >> 4, s = k >> 4;
            const int mat = ((ul & 15) >> 3) | (((k & 15) >> 3) << 1);
            const int off = ((((mt * KSTEPS + s) << 2) + mat) << 6)
                            + ((ul & 7) << 3) + (k & 7);   // bf16 units
            aH[off] = h;
            aL[off] = l;
        }
    }

    const uint32_t aBaseH = sb + SA_HI + lane * 16;
    const uint32_t aBaseL = sb + SA_LO + lane * 16;
    const int L2 = lane & 15;
    const uint32_t bOff = ((L2 >> 3) << 7) + ((L2 & 7) << 4);

    for (int bi = 0; bi < BPC; bi++) {
        const int b = blockIdx.x * BPC + bi;

        // --- x load + hi/lo split ---
        {
            const float* xg = x + (size_t)b * (4 * LIN);
            for (int i = tid; i < 4 * LIN; i += CTHREADS) {
                const float v = xg[i];
                const __nv_bfloat16 h = __float2bfloat16(v);
                xh[i] = h;
                xl[i] = __float2bfloat16(v - __bfloat162float(h));
            }
        }
        __syncthreads();

        // --- loop over 4 pool-chunks ---
        for (int nt = 0; nt < 4; nt++) {
            const int npools = (nt < 3) ? NCHUNK : (LP - 3 * NCHUNK);   // 24,24,24,12

            // build B chunk: pool-major im2col, hi/lo splits
            {
                const int tot = npools * 8 * 80;
                for (int i = tid; i < tot; i += CTHREADS) {
                    const int p  = i / 640;
                    const int r  = i % 640;
                    const int j  = r / 80;           // slot 0..7
                    const int k  = r % 80;
                    const int jj = (j == 7) ? 0 : j; // slot 7 duplicates slot 0
                    __nv_bfloat16 vh = __float2bfloat16(0.f);
                    __nv_bfloat16 vl = vh;
                    if (k < 76) {
                        const int c  = k / FLT, kk = k % FLT;
                        const int xi = c * LIN + 7 * (nt * NCHUNK + p) + jj + kk;
                        vh = xh[xi];
                        vl = xl[xi];
                    }
                    const int off = (((p * KSTEPS + (k >> 4)) << 1) + ((k & 15) >> 3)) * 128
                                    + (j << 4) + ((k & 7) << 1);   // bytes
                    *reinterpret_cast<__nv_bfloat16*>(smem + SB_HI + off) = vh;
                    *reinterpret_cast<__nv_bfloat16*>(smem + SB_LO + off) = vl;
                }
            }
            __syncthreads();

            const bool use2 = (wid + 12 < npools);

            // --- B fragments -> registers (once per chunk) ---
            uint32_t bh[2][KSTEPS][2], bl[2][KSTEPS][2];
#pragma unroll
            for (int r = 0; r < 2; r++) {
                if (r == 0 || use2) {
                    const int pt = wid + 12 * r;
#pragma unroll
                    for (int s = 0; s < KSTEPS; s++) {
                        const uint32_t tb = (pt * KSTEPS + s) * 256 + bOff;
                        LDSM2(bh[r][s], sb + SB_HI + tb);
                        LDSM2(bl[r][s], sb + SB_LO + tb);
                    }
                }
            }

            // --- A double-buffered m-tile stream ---
            uint32_t ah0[KSTEPS][4], al0[KSTEPS][4];
            uint32_t ah1[KSTEPS][4], al1[KSTEPS][4];
#pragma unroll
            for (int s = 0; s < KSTEPS; s++) {
                LDSM4(ah0[s], aBaseH + s * 512);
                LDSM4(al0[s], aBaseL + s * 512);
            }
            for (int mtb = 0; mtb < MTILES; mtb += 2) {
                PROC(mtb, ah0, al0, ah1, al1);
                if (mtb + 1 < MTILES)
                    PROC(mtb + 1, ah1, al1, ah0, al0);
            }
            __syncthreads();
        }
    }
}

// ---------------------------------------------------------------------------
// packed f32x2 helpers (MLP kernel)
// ---------------------------------------------------------------------------
__device__ __forceinline__ u64 pack2(float a, float b) {
    u64 r;
    asm("mov.b64 %0, {%1, %2};" : "=l"(r) : "f"(a), "f"(b));
    return r;
}
__device__ __forceinline__ void fma2(u64 &d, u64 a, u64 b) {
    asm("fma.rn.f32x2 %0, %1, %2, %0;" : "+l"(d) : "l"(a), "l"(b));
}
__device__ __forceinline__ void unpack2(float &lo, float &hi, u64 v) {
    unsigned a, b;
    asm("mov.b64 {%0, %1}, %2;" : "=r"(a), "=r"(b) : "l"(v));
    lo = __uint_as_float(a); hi = __uint_as_float(b);
}

// ---------------------------------------------------------------------------
// Kernel B: per-unit MLP 84->100 (BN+ReLU) -> 100->1 (BN+ReLU)  ->  z[u][b]
// ---------------------------------------------------------------------------
__global__ __launch_bounds__(BATCH) void unit_mlp_kernel(
    const float* __restrict__ w2, const float* __restrict__ b2,
    const float* __restrict__ g2, const float* __restrict__ be2,
    const float* __restrict__ m2, const float* __restrict__ v2,
    const float* __restrict__ w3, const float* __restrict__ b3,
    const float* __restrict__ g3, const float* __restrict__ be3,
    const float* __restrict__ m3, const float* __restrict__ v3)
{
    __shared__ __align__(16) float w2s[HID * LP];
    __shared__ float s2s[HID], c2s[HID], w3s[HID];

    const int u   = blockIdx.x;
    const int tid = threadIdx.x;

    for (int i = tid; i < HID * LP; i += BATCH)
        w2s[i] = w2[u * HID * LP + i];
    if (tid < HID) {
        const int idx = u * HID + tid;
        float s = g2[idx] * rsqrtf(v2[idx] + EPSV);
        s2s[tid] = s;
        c2s[tid] = (b2[idx] - m2[idx]) * s + be2[idx];
        w3s[tid] = w3[idx];
    }
    __syncthreads();

    u64 yv2[LP / 2];
#pragma unroll
    for (int fp = 0; fp < LP / 2; fp++) {
        const float a  = g_y[u * (LP * BATCH) + (2 * fp) * BATCH + tid];
        const float bb = g_y[u * (LP * BATCH) + (2 * fp + 1) * BATCH + tid];
        yv2[fp] = pack2(a, bb);
    }

    float zacc = 0.0f;
#pragma unroll 1
    for (int o = 0; o < HID; o++) {
        const float4* wrow = reinterpret_cast<const float4*>(&w2s[o * LP]);
        u64 a0 = 0ULL, a1 = 0ULL;
#pragma unroll
        for (int j = 0; j < LP / 4; j++) {
            float4 v = wrow[j];
            u64 w01 = pack2(v.x, v.y);
            u64 w23 = pack2(v.z, v.w);
            fma2(a0, yv2[2 * j], w01);
            fma2(a1, yv2[2 * j + 1], w23);
        }
        float l0, h0, l1, h1;
        unpack2(l0, h0, a0);
        unpack2(l1, h1, a1);
        const float dsum = (l0 + h0) + (l1 + h1);
        const float hv = fmaxf(fmaf(dsum, s2s[o], c2s[o]), 0.0f);
        zacc = fmaf(hv, w3s[o], zacc);
    }

    const float s3 = g3[u] * rsqrtf(v3[u] + EPSV);
    const float z  = fmaf(zacc + b3[u] - m3[u], s3, be3[u]);
    g_z[u * BATCH + tid] = fmaxf(z, 0.0f);
}

// ---------------------------------------------------------------------------
// Kernel C: out[b][c] = sum_u z[u][b] * wf[c][u] + bf[c]
// ---------------------------------------------------------------------------
__global__ __launch_bounds__(BATCH) void final_linear_kernel(
    const float* __restrict__ wf, const float* __restrict__ bf,
    float* __restrict__ out)
{
    __shared__ float wfs[NU];
    const int c   = blockIdx.x;
    const int tid = threadIdx.x;

    for (int i = tid; i < NU; i += BATCH)
        wfs[i] = wf[c * NU + i];
    __syncthreads();

    float acc = bf[c];
#pragma unroll 4
    for (int u = 0; u < NU; u++)
        acc = fmaf(g_z[u * BATCH + tid], wfs[u], acc);

    out[tid * NCLS + c] = acc;
}

// ---------------------------------------------------------------------------
extern "C" void kernel_launch(void* const* d_in, const int* in_sizes, int n_in,
                              void* d_out, int out_size)
{
    const float* x   = (const float*)d_in[0];
    const float* w1  = (const float*)d_in[1];
    const float* b1  = (const float*)d_in[2];
    const float* g1  = (const float*)d_in[3];
    const float* be1 = (const float*)d_in[4];
    const float* m1  = (const float*)d_in[5];
    const float* v1  = (const float*)d_in[6];
    const float* w2  = (const float*)d_in[7];
    const float* b2  = (const float*)d_in[8];
    const float* g2  = (const float*)d_in[9];
    const float* be2 = (const float*)d_in[10];
    const float* m2  = (const float*)d_in[11];
    const float* v2  = (const float*)d_in[12];
    const float* w3  = (const float*)d_in[13];
    const float* b3  = (const float*)d_in[14];
    const float* g3  = (const float*)d_in[15];
    const float* be3 = (const float*)d_in[16];
    const float* m3  = (const float*)d_in[17];
    const float* v3  = (const float*)d_in[18];
    const float* wf  = (const float*)d_in[19];
    const float* bf  = (const float*)d_in[20];
    float* out = (float*)d_out;

    cudaFuncSetAttribute(conv_mma_kernel,
                         cudaFuncAttributeMaxDynamicSharedMemorySize, SMTOT);

    conv_mma_kernel<<<BATCH / BPC, CTHREADS, SMTOT>>>(x, w1, b1, g1, be1, m1, v1);
    unit_mlp_kernel<<<NU, BATCH>>>(w2, b2, g2, be2, m2, v2,
                                   w3, b3, g3, be3, m3, v3);
    final_linear_kernel<<<NCLS, BATCH>>>(wf, bf, out);
}